// round 17
// baseline (speedup 1.0000x reference)
#include <cuda_runtime.h>
#include <cuda_fp16.h>
#include <stdint.h>

// Problem dims
#define B_  2
#define S_  2048
#define D_  1024
#define H_  16
#define HD_ 64
#define BS_ (B_ * S_)         // 4096
#define NX  (BS_ * D_)
#define NW  (H_ * D_ * HD_)
#define LOG2E 1.4426950408889634f

// fp16 scratch (device globals — allocation-guard safe)
__device__ __align__(16) __half g_xh[NX];
__device__ __align__(16) __half g_wT[3 * D_ * D_];   // [mat][n=h*64+e][k]
__device__ __align__(16) __half g_woh[D_ * D_];      // [n][k]
__device__ float g_bqs[H_ * HD_];                    // bq * 0.125 * log2e
__device__ __align__(16) __half g_q[B_ * H_ * S_ * HD_];   // exp2-domain pre-scaled
__device__ __align__(16) __half g_k[B_ * H_ * S_ * HD_];
__device__ __align__(16) __half g_v[B_ * H_ * S_ * HD_];
__device__ __align__(16) __half g_wv[BS_ * D_];            // [B,S,H*HD]

__device__ __forceinline__ uint32_t smem_u32(const void* p) {
    uint32_t a;
    asm("{ .reg .u64 t; cvta.to.shared.u64 t, %1; cvt.u32.u64 %0, t; }"
        : "=r"(a) : "l"(p));
    return a;
}

__device__ __forceinline__ void mma_f16(float c[4], const uint32_t a[4],
                                        uint32_t b0, uint32_t b1) {
    asm volatile(
        "mma.sync.aligned.m16n8k16.row.col.f32.f16.f16.f32 "
        "{%0,%1,%2,%3}, {%4,%5,%6,%7}, {%8,%9}, {%0,%1,%2,%3};"
        : "+f"(c[0]), "+f"(c[1]), "+f"(c[2]), "+f"(c[3])
        : "r"(a[0]), "r"(a[1]), "r"(a[2]), "r"(a[3]), "r"(b0), "r"(b1));
}
__device__ __forceinline__ void ldm4(uint32_t r[4], uint32_t addr) {
    asm volatile("ldmatrix.sync.aligned.m8n8.x4.shared.b16 {%0,%1,%2,%3}, [%4];"
        : "=r"(r[0]), "=r"(r[1]), "=r"(r[2]), "=r"(r[3]) : "r"(addr));
}
__device__ __forceinline__ void ldm4t(uint32_t r[4], uint32_t addr) {
    asm volatile("ldmatrix.sync.aligned.m8n8.x4.trans.shared.b16 {%0,%1,%2,%3}, [%4];"
        : "=r"(r[0]), "=r"(r[1]), "=r"(r[2]), "=r"(r[3]) : "r"(addr));
}

#define CP16(d, s)  asm volatile("cp.async.cg.shared.global [%0], [%1], 16;" :: "r"(d), "l"(s))
#define CPCOMMIT()  asm volatile("cp.async.commit_group;")
#define CPWAIT(n)   asm volatile("cp.async.wait_group %0;" :: "n"(n))

#define PK2(x, y) ({ __half2 _h = __floats2half2_rn((x), (y)); *(uint32_t*)&_h; })

// ---------------------------------------------------------------------------
// Convert (vectorized): x -> fp16, Wo -> fp16 [n][k], bq scaled
// ---------------------------------------------------------------------------
#define NX4 (NX / 4)
#define ND4 (D_ * D_ / 4)
__device__ __forceinline__ void cvt4(__half* dst, const float* src, long long i, float s) {
    float4 v = ((const float4*)src)[i];
    __half2 h0 = __floats2half2_rn(v.x * s, v.y * s);
    __half2 h1 = __floats2half2_rn(v.z * s, v.w * s);
    ((uint2*)dst)[i] = make_uint2(*(uint32_t*)&h0, *(uint32_t*)&h1);
}
__global__ __launch_bounds__(256) void convert_kernel(
    const float* __restrict__ x, const float* __restrict__ bq,
    const float* __restrict__ Wo)
{
    long long i = (long long)blockIdx.x * 256 + threadIdx.x;
    if (i < NX4) { cvt4(g_xh, x, i, 1.f); return; }
    i -= NX4;
    if (i < ND4) { cvt4(g_woh, Wo, i, 1.f); return; }
    i -= ND4;
    if (i < H_ * HD_) g_bqs[i] = bq[i] * 0.125f * LOG2E;
}

// ---------------------------------------------------------------------------
// Transpose-convert Wq/Wk/Wv [h][d][e] -> g_wT [mat][h*64+e][k=d] fp16
// (Wq folds 0.125*log2e). Validated in R14. grid (16,16,3), 256 thr.
// ---------------------------------------------------------------------------
__global__ __launch_bounds__(256) void convertW_kernel(
    const float* __restrict__ Wq, const float* __restrict__ Wk,
    const float* __restrict__ Wv)
{
    __shared__ float t[64][65];
    const int dt = blockIdx.x, h = blockIdx.y, m = blockIdx.z;
    const float* W = (m == 0) ? Wq : (m == 1) ? Wk : Wv;
    const float sc = (m == 0) ? 0.125f * LOG2E : 1.f;
    const int tid = threadIdx.x;
    #pragma unroll
    for (int i = 0; i < 16; i++) {
        int g = i * 256 + tid;
        int dl = g >> 6, e = g & 63;
        t[dl][e] = W[((size_t)h * D_ + dt * 64 + dl) * HD_ + e];
    }
    __syncthreads();
    __half* dst = g_wT + (size_t)m * D_ * D_;
    #pragma unroll
    for (int i = 0; i < 16; i++) {
        int g = i * 256 + tid;
        int e = g >> 6, dl = g & 63;
        dst[((size_t)(h * 64 + e)) * D_ + dt * 64 + dl] = __float2half_rn(t[dl][e] * sc);
    }
}

// ---------------------------------------------------------------------------
// GEMM skeleton (= proven oproj): 512 threads, 128x256x32, warp tile 32x64.
// A [row][k], B [n][k] stride 40 halves, non-trans ldmatrix. 3-buffer ring.
// ---------------------------------------------------------------------------
#define GA_ST 40
#define GAW   (128 * GA_ST)
#define GBW   (256 * GA_ST)
#define GSTG  (GAW + GBW)
#define GEMM_SMEM (3 * GSTG * 2)   // 92160 bytes

#define G_STAGE(c, s) {                                                        \
    uint32_t sb = sm0 + (s) * GSTG * 2;                                        \
    {   int g = tid; int row = g >> 2; int kg = (g & 3) * 8;                   \
        CP16(sb + (row * GA_ST + kg) * 2,                                      \
             Ap + (size_t)row * D_ + (c) * 32 + kg);                           \
    }                                                                          \
    _Pragma("unroll")                                                          \
    for (int i = 0; i < 2; i++) {                                              \
        int g = i * 512 + tid; int n = g >> 2; int kg = (g & 3) * 8;           \
        CP16(sb + (GAW + n * GA_ST + kg) * 2,                                  \
             Bp + (size_t)n * D_ + (c) * 32 + kg);                             \
    } }

#define G_BODY()                                                               \
    const int tid  = threadIdx.x;                                              \
    const int wid  = tid >> 5;                                                 \
    const int lane = tid & 31;                                                 \
    const int wm   = wid >> 2, wn = wid & 3;                                   \
    const int ql   = lane & 3, qr = lane >> 2;                                 \
    const uint32_t sm0 = smem_u32(hsm);                                        \
    const uint32_t aLane = ((wm * 32 + (lane & 15)) * GA_ST) * 2 + (lane >> 4) * 16; \
    const uint32_t bLane = ((wn * 64 + (lane & 15)) * GA_ST) * 2 + (lane >> 4) * 16; \
    float acc[2][8][4];                                                        \
    _Pragma("unroll")                                                          \
    for (int mi = 0; mi < 2; mi++)                                             \
        _Pragma("unroll")                                                      \
        for (int ni = 0; ni < 8; ni++)                                         \
            _Pragma("unroll")                                                  \
            for (int c = 0; c < 4; c++) acc[mi][ni][c] = 0.f;                  \
    G_STAGE(0, 0); CPCOMMIT();                                                 \
    G_STAGE(1, 1); CPCOMMIT();                                                 \
    for (int c = 0; c < 32; c++) {                                             \
        const int cur = c % 3;                                                 \
        CPWAIT(1);                                                             \
        __syncthreads();                                                       \
        if (c + 2 < 32) { G_STAGE(c + 2, (c + 2) % 3); }                       \
        CPCOMMIT();                                                            \
        const uint32_t sAb = sm0 + cur * GSTG * 2;                             \
        const uint32_t sBb = sAb + GAW * 2;                                    \
        _Pragma("unroll")                                                      \
        for (int kk = 0; kk < 2; kk++) {                                       \
            uint32_t a[2][4];                                                  \
            _Pragma("unroll")                                                  \
            for (int mi = 0; mi < 2; mi++)                                     \
                ldm4(a[mi], sAb + aLane + mi * 16 * GA_ST * 2 + kk * 32);      \
            uint32_t bb[4][4];                                                 \
            _Pragma("unroll")                                                  \
            for (int nj = 0; nj < 4; nj++)                                     \
                ldm4(bb[nj], sBb + bLane + nj * 16 * GA_ST * 2 + kk * 32);     \
            _Pragma("unroll")                                                  \
            for (int mi = 0; mi < 2; mi++)                                     \
                _Pragma("unroll")                                              \
                for (int nj = 0; nj < 4; nj++) {                               \
                    mma_f16(acc[mi][2 * nj],     a[mi], bb[nj][0], bb[nj][2]); \
                    mma_f16(acc[mi][2 * nj + 1], a[mi], bb[nj][1], bb[nj][3]); \
                }                                                              \
        }                                                                      \
    }

// ---------------------------------------------------------------------------
// QKV projection: oproj-style GEMM on transposed weights. grid (32, 4, 3).
// ---------------------------------------------------------------------------
__global__ __launch_bounds__(512, 1) void qkv_kernel(
    const float* __restrict__ bk, const float* __restrict__ bv)
{
    extern __shared__ __half hsm[];
    const int rt = blockIdx.x, ct = blockIdx.y, m = blockIdx.z;
    const __half* Ap = g_xh + (size_t)(rt * 128) * D_;
    const __half* Bp = g_wT + ((size_t)m * D_ + ct * 256) * D_;
    const float* bias = (m == 0) ? g_bqs : (m == 1) ? bk : bv;
    __half* out = (m == 0) ? g_q : (m == 1) ? g_k : g_v;

    G_BODY();

    // epilogue: [B,H,S,HD] fp16 + bias
    const int h0 = ct * 4;
    #pragma unroll
    for (int mi = 0; mi < 2; mi++) {
        int row = rt * 128 + wm * 32 + mi * 16 + qr;
        int bb2 = row >> 11;
        int s   = row & (S_ - 1);
        #pragma unroll
        for (int ni = 0; ni < 8; ni++) {
            int cl = wn * 64 + ni * 8 + 2 * ql;
            int h  = h0 + (cl >> 6);
            int e  = cl & 63;
            float bv0 = bias[h * HD_ + e];
            float bv1 = bias[h * HD_ + e + 1];
            __half* p0 = out + (((size_t)bb2 * H_ + h) * S_ + s) * HD_ + e;
            __half* p1 = out + (((size_t)bb2 * H_ + h) * S_ + s + 8) * HD_ + e;
            *(__half2*)p0 = __floats2half2_rn(acc[mi][ni][0] + bv0, acc[mi][ni][1] + bv1);
            *(__half2*)p1 = __floats2half2_rn(acc[mi][ni][2] + bv0, acc[mi][ni][3] + bv1);
        }
    }
}

// ---------------------------------------------------------------------------
// Output projection. grid (32, 4).
// ---------------------------------------------------------------------------
__global__ __launch_bounds__(512, 1) void oproj_kernel(
    const float* __restrict__ bo, float* __restrict__ out)
{
    extern __shared__ __half hsm[];
    const int rt = blockIdx.x, ct = blockIdx.y;
    const __half* Ap = g_wv + (size_t)(rt * 128) * D_;
    const __half* Bp = g_woh + (size_t)(ct * 256) * D_;

    G_BODY();

    #pragma unroll
    for (int mi = 0; mi < 2; mi++) {
        int row = rt * 128 + wm * 32 + mi * 16 + qr;
        #pragma unroll
        for (int ni = 0; ni < 8; ni++) {
            int col = ct * 256 + wn * 64 + ni * 8 + 2 * ql;
            float bv0 = bo[col], bv1 = bo[col + 1];
            *(float2*)&out[(size_t)row * D_ + col] =
                make_float2(acc[mi][ni][0] + bv0, acc[mi][ni][1] + bv1);
            *(float2*)&out[(size_t)(row + 8) * D_ + col] =
                make_float2(acc[mi][ni][2] + bv0, acc[mi][ni][3] + bv1);
        }
    }
}

// ---------------------------------------------------------------------------
// Flash attention (causal, fp16, exp2-domain, no running max, P in regs).
// 128-key STAGING tiles (half the barriers), inner compute in 64-key halves.
// 128 queries/block, 8 warps x 16 rows, double-buffered K/V, occ 2.
// grid (16 reversed, 32), 256 threads. smem 92160 B.
// ---------------------------------------------------------------------------
#define AT_ST 72
#define AKV_W (128 * AT_ST)             // 9216 halves per K (or V) buffer
#define AQ_OFF (4 * AKV_W)              // after K0,K1,V0,V1
#define AQ_W  (128 * AT_ST)
#define ATT_SMEM ((AQ_OFF + AQ_W) * 2)  // 92160 bytes

__global__ __launch_bounds__(256, 2) void attn_kernel()
{
    extern __shared__ __half hsm[];

    const int qt = 15 - blockIdx.x;
    const int bh = blockIdx.y;
    const int b  = bh >> 4;
    const int h  = bh & 15;
    const int tid  = threadIdx.x;
    const int w    = tid >> 5;
    const int lane = tid & 31;
    const int qr   = lane >> 2;
    const int ql   = lane & 3;

    const __half* Qb = g_q + (size_t)bh * S_ * HD_;
    const __half* Kb = g_k + (size_t)bh * S_ * HD_;
    const __half* Vb = g_v + (size_t)bh * S_ * HD_;

    const uint32_t sk_b = smem_u32(hsm);
    const uint32_t sv_b = sk_b + 2 * AKV_W * 2;
    const uint32_t sq_b = sk_b + AQ_OFF * 2;
    const uint32_t aoff = ((w * 16 + (lane & 15)) * AT_ST) * 2 + (lane >> 4) * 16;
    const uint32_t koff = ((lane & 15) * AT_ST) * 2 + (lane >> 4) * 16;
    const int klane = (lane & 7) + ((lane >> 3) & 1) * 8;
    const uint32_t voff = (klane * AT_ST + (lane >> 4) * 8) * 2;

    // ---- stage Q, extract A fragments ----
    #pragma unroll
    for (int i = 0; i < 4; i++) {
        int g = i * 256 + tid;
        int row = g >> 3, kg = (g & 7) * 8;
        CP16(sq_b + (row * AT_ST + kg) * 2, &Qb[(size_t)(qt * 128 + row) * HD_ + kg]);
    }
    CPCOMMIT(); CPWAIT(0);
    __syncthreads();

    uint32_t qa[4][4];
    #pragma unroll
    for (int kk = 0; kk < 4; kk++) ldm4(qa[kk], sq_b + aoff + kk * 32);

    // stage 128 K rows + 128 V rows (8 CP16/thread)
    #define ATT_STAGE(kt2, s) {                                                \
        _Pragma("unroll")                                                      \
        for (int i = 0; i < 8; i++) {                                          \
            int g = i * 256 + tid;       /* 0..2047 */                         \
            int sel = g >> 10; int row = (g >> 3) & 127; int kg = (g & 7) * 8; \
            uint32_t base = sel ? (sv_b + (s) * AKV_W * 2) : (sk_b + (s) * AKV_W * 2); \
            const __half* src = sel ? &Vb[(size_t)((kt2) * 128 + row) * HD_ + kg] \
                                    : &Kb[(size_t)((kt2) * 128 + row) * HD_ + kg]; \
            CP16(base + (row * AT_ST + kg) * 2, src);                          \
        }                                                                      \
    }

    ATT_STAGE(0, 0); CPCOMMIT();

    float O[8][4];
    #pragma unroll
    for (int n = 0; n < 8; n++)
        #pragma unroll
        for (int c = 0; c < 4; c++) O[n][c] = 0.f;
    float l0 = 0.f, l1 = 0.f;

    const int rbase = qt * 128 + w * 16;

    for (int kt2 = 0; kt2 <= qt; kt2++) {
        const int buf = kt2 & 1;
        CPWAIT(0);
        __syncthreads();
        if (kt2 + 1 <= qt) { ATT_STAGE(kt2 + 1, buf ^ 1); }
        CPCOMMIT();

        #pragma unroll
        for (int hh = 0; hh < 2; hh++) {
            const int j0 = kt2 * 128 + hh * 64;
            if (j0 > rbase + 15) continue;   // fully masked for this warp

            const uint32_t kbase = sk_b + (buf * AKV_W + hh * 64 * AT_ST) * 2;
            float sc[8][4];
            #pragma unroll
            for (int n = 0; n < 8; n++)
                #pragma unroll
                for (int c = 0; c < 4; c++) sc[n][c] = 0.f;
            #pragma unroll
            for (int kk = 0; kk < 4; kk++) {
                #pragma unroll
                for (int j = 0; j < 4; j++) {
                    uint32_t kb[4];
                    ldm4(kb, kbase + koff + j * 16 * AT_ST * 2 + kk * 32);
                    mma_f16(sc[2 * j],     qa[kk], kb[0], kb[2]);
                    mma_f16(sc[2 * j + 1], qa[kk], kb[1], kb[3]);
                }
            }

            if (j0 + 63 > rbase) {           // partial causal mask
                const int r0 = rbase + qr;
                #pragma unroll
                for (int n = 0; n < 8; n++) {
                    int cg = j0 + n * 8 + 2 * ql;
                    if (cg     > r0)     sc[n][0] = -1e30f;
                    if (cg + 1 > r0)     sc[n][1] = -1e30f;
                    if (cg     > r0 + 8) sc[n][2] = -1e30f;
                    if (cg + 1 > r0 + 8) sc[n][3] = -1e30f;
                }
            }

            // p = exp2(s), accumulate sums, pack to fp16 A-frags immediately
            uint32_t pa[4][4];
            #pragma unroll
            for (int kk = 0; kk < 4; kk++) {
                float e00 = exp2f(sc[2 * kk][0]),     e01 = exp2f(sc[2 * kk][1]);
                float e02 = exp2f(sc[2 * kk][2]),     e03 = exp2f(sc[2 * kk][3]);
                float e10 = exp2f(sc[2 * kk + 1][0]), e11 = exp2f(sc[2 * kk + 1][1]);
                float e12 = exp2f(sc[2 * kk + 1][2]), e13 = exp2f(sc[2 * kk + 1][3]);
                l0 += e00 + e01 + e10 + e11;
                l1 += e02 + e03 + e12 + e13;
                pa[kk][0] = PK2(e00, e01);
                pa[kk][1] = PK2(e02, e03);
                pa[kk][2] = PK2(e10, e11);
                pa[kk][3] = PK2(e12, e13);
            }

            // P @ V
            const uint32_t vbase = sv_b + (buf * AKV_W + hh * 64 * AT_ST) * 2;
            #pragma unroll
            for (int kk = 0; kk < 4; kk++) {
                #pragma unroll
                for (int j = 0; j < 4; j++) {
                    uint32_t vb[4];
                    ldm4t(vb, vbase + voff + (kk * 16 * AT_ST + j * 16) * 2);
                    mma_f16(O[2 * j],     pa[kk], vb[0], vb[1]);
                    mma_f16(O[2 * j + 1], pa[kk], vb[2], vb[3]);
                }
            }
        }
    }

    // ---- reduce l across the quad, normalize, store ----
    l0 += __shfl_xor_sync(0xffffffffu, l0, 1);
    l0 += __shfl_xor_sync(0xffffffffu, l0, 2);
    l1 += __shfl_xor_sync(0xffffffffu, l1, 1);
    l1 += __shfl_xor_sync(0xffffffffu, l1, 2);
    float inv0 = 1.f / l0, inv1 = 1.f / l1;
    int r0g = qt * 128 + w * 16 + qr;
    __half* base0 = g_wv + ((size_t)b * S_ + r0g) * D_ + h * HD_;
    __half* base1 = g_wv + ((size_t)b * S_ + r0g + 8) * D_ + h * HD_;
    #pragma unroll
    for (int n = 0; n < 8; n++) {
        int cc = n * 8 + 2 * ql;
        *(__half2*)&base0[cc] = __floats2half2_rn(O[n][0] * inv0, O[n][1] * inv0);
        *(__half2*)&base1[cc] = __floats2half2_rn(O[n][2] * inv1, O[n][3] * inv1);
    }
}

// ---------------------------------------------------------------------------
// Launch. metadata order: x, Wq, bq, Wk, bk, Wv, bv, Wo, bo
// ---------------------------------------------------------------------------
extern "C" void kernel_launch(void* const* d_in, const int* in_sizes, int n_in,
                              void* d_out, int out_size)
{
    const float* x  = (const float*)d_in[0];
    const float* Wq = (const float*)d_in[1];
    const float* bq = (const float*)d_in[2];
    const float* Wk = (const float*)d_in[3];
    const float* bk = (const float*)d_in[4];
    const float* Wv = (const float*)d_in[5];
    const float* bv = (const float*)d_in[6];
    const float* Wo = (const float*)d_in[7];
    const float* bo = (const float*)d_in[8];
    float* out = (float*)d_out;

    cudaFuncSetAttribute(qkv_kernel,   cudaFuncAttributeMaxDynamicSharedMemorySize, GEMM_SMEM);
    cudaFuncSetAttribute(attn_kernel,  cudaFuncAttributeMaxDynamicSharedMemorySize, ATT_SMEM);
    cudaFuncSetAttribute(oproj_kernel, cudaFuncAttributeMaxDynamicSharedMemorySize, GEMM_SMEM);

    const long long ntot = (long long)NX4 + ND4 + H_ * HD_;
    convert_kernel<<<(int)((ntot + 255) / 256), 256>>>(x, bq, Wo);
    convertW_kernel<<<dim3(16, 16, 3), 256>>>(Wq, Wk, Wv);

    qkv_kernel<<<dim3(BS_ / 128, D_ / 256, 3), 512, GEMM_SMEM>>>(bk, bv);

    attn_kernel<<<dim3(16, 32), 256, ATT_SMEM>>>();

    oproj_kernel<<<dim3(BS_ / 128, D_ / 256), 512, GEMM_SMEM>>>(bo, out);
}